// round 14
// baseline (speedup 1.0000x reference)
#include <cuda_runtime.h>
#include <cuda_fp16.h>
#include <math.h>
#include <stddef.h>
#include <stdint.h>

typedef unsigned long long ull;

#define T_DIM 4096
#define H_DIM 2048
#define K_DIM 1024
#define V_DIM 1024
#define O_DIM 2048
#define CHUNK 32
#define NCHUNK 128

// fp32 scratch: q | k | g | v | qa | kia | opre | a15 | sdump
__device__ __align__(16) float g_scratch[(size_t)5 * T_DIM * K_DIM +
                                         (size_t)2 * T_DIM * V_DIM +
                                         (size_t)NCHUNK * K_DIM +
                                         (size_t)K_DIM * V_DIM];
// fp16 scratch: Xh | Wall | Woh | opreh | qah | khT | vT | snap
__device__ __align__(16) __half g_scratch_h[(size_t)T_DIM * H_DIM +
                                            (size_t)4 * K_DIM * H_DIM +
                                            (size_t)O_DIM * V_DIM +
                                            (size_t)T_DIM * V_DIM +
                                            (size_t)3 * T_DIM * K_DIM +
                                            (size_t)NCHUNK * K_DIM * V_DIM];

// ---------------- helpers ----------------
__device__ __forceinline__ uint32_t smem_u32(const void* p) {
    return (uint32_t)__cvta_generic_to_shared(p);
}
__device__ __forceinline__ void ldm_x4(uint32_t* r, const __half* p) {
    uint32_t addr = smem_u32(p);
    asm volatile("ldmatrix.sync.aligned.m8n8.x4.shared.b16 {%0,%1,%2,%3}, [%4];"
                 : "=r"(r[0]), "=r"(r[1]), "=r"(r[2]), "=r"(r[3]) : "r"(addr));
}
__device__ __forceinline__ void mma16816(float* d, const uint32_t* a, const uint32_t* b) {
    asm volatile(
        "mma.sync.aligned.m16n8k16.row.col.f32.f16.f16.f32 "
        "{%0,%1,%2,%3}, {%4,%5,%6,%7}, {%8,%9}, {%0,%1,%2,%3};"
        : "+f"(d[0]), "+f"(d[1]), "+f"(d[2]), "+f"(d[3])
        : "r"(a[0]), "r"(a[1]), "r"(a[2]), "r"(a[3]), "r"(b[0]), "r"(b[1]));
}
__device__ __forceinline__ void cp_async16(__half* smem_dst, const __half* gsrc) {
    asm volatile("cp.async.cg.shared.global [%0], [%1], 16;"
                 :: "r"(smem_u32(smem_dst)), "l"(gsrc));
}
__device__ __forceinline__ void cp_async16_g(void* smem_dst, const void* gsrc) {
    asm volatile("cp.async.cg.shared.global [%0], [%1], 16;"
                 :: "r"(smem_u32(smem_dst)), "l"(gsrc));
}
#define CP_COMMIT() asm volatile("cp.async.commit_group;")
#define CP_WAIT(n)  asm volatile("cp.async.wait_group %0;" :: "n"(n))

// ---------------- fp32 -> fp16 convert (single + batched x4) ----------------
__global__ void f2h_kernel(const float* __restrict__ src, __half* __restrict__ dst, int n4)
{
    int i = blockIdx.x * blockDim.x + threadIdx.x;
    const int stride = gridDim.x * blockDim.x;
    for (; i < n4; i += stride) {
        float4 v = ((const float4*)src)[i];
        __half2 h0 = __floats2half2_rn(v.x, v.y);
        __half2 h1 = __floats2half2_rn(v.z, v.w);
        uint2 u;
        u.x = *reinterpret_cast<unsigned*>(&h0);
        u.y = *reinterpret_cast<unsigned*>(&h1);
        ((uint2*)dst)[i] = u;
    }
}
__global__ void f2h4_kernel(const float* __restrict__ s0, const float* __restrict__ s1,
                            const float* __restrict__ s2, const float* __restrict__ s3,
                            __half* __restrict__ dst, int n4)
{
    const float* src = (blockIdx.y == 0) ? s0 : (blockIdx.y == 1) ? s1
                       : (blockIdx.y == 2) ? s2 : s3;
    __half* d = dst + (size_t)blockIdx.y * (size_t)n4 * 4;
    int i = blockIdx.x * blockDim.x + threadIdx.x;
    const int stride = gridDim.x * blockDim.x;
    for (; i < n4; i += stride) {
        float4 v = ((const float4*)src)[i];
        __half2 h0 = __floats2half2_rn(v.x, v.y);
        __half2 h1 = __floats2half2_rn(v.z, v.w);
        uint2 u;
        u.x = *reinterpret_cast<unsigned*>(&h0);
        u.y = *reinterpret_cast<unsigned*>(&h1);
        ((uint2*)d)[i] = u;
    }
}

// ---------------- wide fp16 NT GEMM: CTA 128x256, warp tile 64x64 -----------
// mma/ldmatrix ratio 4.0 (vs 2.67 at 64x32): smem-read pressure halves per
// FLOP, so the legacy HMMA pipe becomes the sole binder. 1 CTA/SM via 61.4KB
// dynamic smem (proven cudaFuncSetAttribute pattern).
#define KP 40
#define G_DSMEM 61440   // As[2][128*KP] + Bs[2][256*KP] halves

struct EpiPlain {
    const float* bias; float* C; int N; int act;
    __device__ __forceinline__ void store(int row, int col, float c0, float c1) const {
        c0 += __ldg(&bias[col]); c1 += __ldg(&bias[col + 1]);
        if (act) { c0 = 1.f / (1.f + expf(-c0)); c1 = 1.f / (1.f + expf(-c1)); }
        *(float2*)(C + (size_t)row * N + col) = make_float2(c0, c1);
    }
};
// routed epilogue: col>>10 selects one of 4 outputs (k,g get sigmoid)
struct EpiRoute {
    const float* b0; const float* b1; const float* b2; const float* b3;
    float* d0; float* d1; float* d2; float* d3;
    __device__ __forceinline__ void store(int row, int col, float c0, float c1) const {
        const int sel = col >> 10;
        const int lc = col & 1023;
        const float* bias = (sel == 0) ? b0 : (sel == 1) ? b1 : (sel == 2) ? b2 : b3;
        float* C = (sel == 0) ? d0 : (sel == 1) ? d1 : (sel == 2) ? d2 : d3;
        c0 += __ldg(&bias[lc]); c1 += __ldg(&bias[lc + 1]);
        if (sel == 1 || sel == 2) {
            c0 = 1.f / (1.f + expf(-c0)); c1 = 1.f / (1.f + expf(-c1));
        }
        *(float2*)(C + (size_t)row * 1024 + lc) = make_float2(c0, c1);
    }
};

template <class Epi>
__device__ __forceinline__ void gemm_body_wide(
    const __half* __restrict__ A, const __half* __restrict__ B,
    int Kd, int bm, int bn, const Epi& epi)
{
    extern __shared__ __half gsm[];
    __half* AsB = gsm;                    // 2 x 128*KP
    __half* BsB = gsm + 2 * 128 * KP;     // 2 x 256*KP

    const int tid = threadIdx.x;
    const int lane = tid & 31;
    const int wid = tid >> 5;
    const int warpM = wid >> 2;     // 0..1 -> 64 rows each
    const int warpN = wid & 3;      // 0..3 -> 64 cols each

    float acc[4][8][4];
#pragma unroll
    for (int a = 0; a < 4; a++)
#pragma unroll
        for (int b = 0; b < 8; b++)
#pragma unroll
            for (int c = 0; c < 4; c++) acc[a][b][c] = 0.f;

    const int iters = Kd / 32;

#define LOAD_TILE_W(buf, k0)                                                   \
    {                                                                          \
        __half* Asb = AsB + (buf) * 128 * KP;                                  \
        __half* Bsb = BsB + (buf) * 256 * KP;                                  \
        _Pragma("unroll")                                                      \
        for (int p = 0; p < 2; p++) {                                          \
            const int c = tid + p * 256;                                       \
            const int row = c >> 2;                                            \
            const int col = (c & 3) * 8;                                       \
            cp_async16(&Asb[row * KP + col],                                   \
                       A + (size_t)(bm + row) * Kd + (k0) + col);              \
        }                                                                      \
        _Pragma("unroll")                                                      \
        for (int p = 0; p < 4; p++) {                                          \
            const int c = tid + p * 256;                                       \
            const int row = c >> 2;                                            \
            const int col = (c & 3) * 8;                                       \
            cp_async16(&Bsb[row * KP + col],                                   \
                       B + (size_t)(bn + row) * Kd + (k0) + col);              \
        }                                                                      \
    }

    LOAD_TILE_W(0, 0);
    CP_COMMIT();

    for (int it = 0; it < iters; ++it) {
        if (it + 1 < iters) {
            LOAD_TILE_W((it + 1) & 1, (it + 1) * 32);
            CP_COMMIT();
            CP_WAIT(1);
        } else {
            CP_WAIT(0);
        }
        __syncthreads();

        const __half* Ab = AsB + (it & 1) * 128 * KP;
        const __half* Bb = BsB + (it & 1) * 256 * KP;
#pragma unroll
        for (int ks = 0; ks < 2; ks++) {
            const int k0 = ks * 16;
            uint32_t afr[4][4];
            uint32_t bfr[8][2];
#pragma unroll
            for (int fm = 0; fm < 4; fm++) {
                const __half* p = &Ab[(warpM * 64 + fm * 16 + (lane & 7) +
                                       ((lane >> 3) & 1) * 8) * KP +
                                      k0 + (lane >> 4) * 8];
                ldm_x4(afr[fm], p);
            }
#pragma unroll
            for (int fp = 0; fp < 4; fp++) {
                uint32_t r[4];
                const __half* p = &Bb[(warpN * 64 + fp * 16 + (lane & 7) +
                                       (lane >> 4) * 8) * KP +
                                      k0 + ((lane >> 3) & 1) * 8];
                ldm_x4(r, p);
                bfr[2 * fp][0] = r[0];     bfr[2 * fp][1] = r[1];
                bfr[2 * fp + 1][0] = r[2]; bfr[2 * fp + 1][1] = r[3];
            }
#pragma unroll
            for (int fm = 0; fm < 4; fm++)
#pragma unroll
                for (int fn = 0; fn < 8; fn++)
                    mma16816(acc[fm][fn], afr[fm], bfr[fn]);
        }
        __syncthreads();
    }
#undef LOAD_TILE_W

#pragma unroll
    for (int fm = 0; fm < 4; fm++)
#pragma unroll
        for (int fn = 0; fn < 8; fn++)
#pragma unroll
            for (int h = 0; h < 2; h++) {
                const int row = bm + warpM * 64 + fm * 16 + (lane >> 2) + h * 8;
                const int col = bn + warpN * 64 + fn * 8 + (lane & 3) * 2;
                epi.store(row, col, acc[fm][fn][2 * h], acc[fm][fn][2 * h + 1]);
            }
}

__global__ void __launch_bounds__(256, 1) gemm_h_nt(
    const __half* __restrict__ A, const __half* __restrict__ B,
    const float* __restrict__ bias, float* __restrict__ C,
    int M, int N, int Kd, int act)
{
    EpiPlain epi{bias, C, N, act};
    gemm_body_wide(A, B, Kd, blockIdx.y * 128, blockIdx.x * 256, epi);
}

// merged 4-projection GEMM: B = stacked [Wq;Wk;Wg;Wv] (4096 x 2048), routed epi
__global__ void __launch_bounds__(256, 1) gemm_h_nt_proj(
    const __half* __restrict__ A, const __half* __restrict__ Wall,
    const float* bq, const float* bk, const float* bg, const float* bv,
    float* qb, float* kb, float* gb, float* vb)
{
    EpiRoute epi{bq, bk, bg, bv, qb, kb, gb, vb};
    gemm_body_wide(A, Wall, H_DIM, blockIdx.y * 128, blockIdx.x * 256, epi);
}

// ---------------- prep: per-chunk cumulative gates ----------------
__global__ void __launch_bounds__(256) prep_kernel(
    const float* __restrict__ q, const float* __restrict__ kk,
    const float* __restrict__ g, const float* __restrict__ vv,
    float* __restrict__ qa, __half* __restrict__ qah,
    float* __restrict__ kia, float* __restrict__ a15,
    __half* __restrict__ khT, __half* __restrict__ vT)
{
    const int cid = blockIdx.x;
    const int kc = threadIdx.x * 4;
    const size_t t0 = (size_t)cid * CHUNK;
    float4 A = make_float4(1.f, 1.f, 1.f, 1.f);
#pragma unroll 4
    for (int u = 0; u < CHUNK; u++) {
        const size_t off = (t0 + u) * K_DIM + kc;
        float4 gv = *(const float4*)(g + off);
        A.x *= gv.x; A.y *= gv.y; A.z *= gv.z; A.w *= gv.w;
        float4 qv = *(const float4*)(q + off);
        float4 qa4 = make_float4(qv.x * A.x, qv.y * A.y, qv.z * A.z, qv.w * A.w);
        *(float4*)(qa + off) = qa4;
        __half2 h0 = __floats2half2_rn(qa4.x, qa4.y);
        __half2 h1 = __floats2half2_rn(qa4.z, qa4.w);
        uint2 uu; uu.x = *(unsigned*)&h0; uu.y = *(unsigned*)&h1;
        *(uint2*)(qah + off) = uu;
        float4 kv = *(const float4*)(kk + off);
        float4 ki = make_float4(__fdiv_rn(kv.x, A.x), __fdiv_rn(kv.y, A.y),
                                __fdiv_rn(kv.z, A.z), __fdiv_rn(kv.w, A.w));
        *(float4*)(kia + off) = ki;
    }
    *(float4*)(a15 + (size_t)cid * K_DIM + kc) = A;

    {
        uint32_t buf[4][16];
        float prev[4];
#pragma unroll
        for (int u = 0; u < CHUNK; u++) {
            const size_t off = (t0 + u) * K_DIM + kc;
            float4 ki = *(const float4*)(kia + off);
            float cur[4] = {ki.x * A.x, ki.y * A.y, ki.z * A.z, ki.w * A.w};
            if (u & 1) {
#pragma unroll
                for (int j = 0; j < 4; j++) {
                    __half2 h = __floats2half2_rn(prev[j], cur[j]);
                    buf[j][u >> 1] = *(unsigned*)&h;
                }
            } else {
#pragma unroll
                for (int j = 0; j < 4; j++) prev[j] = cur[j];
            }
        }
#pragma unroll
        for (int j = 0; j < 4; j++) {
            __half* dst = khT + ((size_t)cid * K_DIM + kc + j) * CHUNK;
#pragma unroll
            for (int c = 0; c < 4; c++)
                *(uint4*)(dst + c * 8) = *(uint4*)&buf[j][c * 4];
        }
    }
    {
        uint32_t buf[4][16];
        float prev[4];
#pragma unroll
        for (int u = 0; u < CHUNK; u++) {
            float4 v4 = *(const float4*)(vv + (t0 + u) * V_DIM + kc);
            float cur[4] = {v4.x, v4.y, v4.z, v4.w};
            if (u & 1) {
#pragma unroll
                for (int j = 0; j < 4; j++) {
                    __half2 h = __floats2half2_rn(prev[j], cur[j]);
                    buf[j][u >> 1] = *(unsigned*)&h;
                }
            } else {
#pragma unroll
                for (int j = 0; j < 4; j++) prev[j] = cur[j];
            }
        }
#pragma unroll
        for (int j = 0; j < 4; j++) {
            __half* dst = vT + ((size_t)cid * V_DIM + kc + j) * CHUNK;
#pragma unroll
            for (int c = 0; c < 4; c++)
                *(uint4*)(dst + c * 8) = *(uint4*)&buf[j][c * 4];
        }
    }
}

// ---------------- intra-chunk: P = QA @ KIA^T (masked), out = P @ V ----------
#define TS 128
__global__ void __launch_bounds__(256) intra_kernel(
    const float* __restrict__ qa, const float* __restrict__ kia,
    const float* __restrict__ vv, float* __restrict__ opre)
{
    __shared__ float qs[CHUNK][TS + 4];
    __shared__ float ks_[CHUNK][TS + 4];
    __shared__ float Ps[CHUNK][CHUNK + 1];
    const int tid = threadIdx.x;
    const int cid = blockIdx.x;
    const size_t t0 = (size_t)cid * CHUNK;

    for (int i = tid; i < CHUNK * (CHUNK + 1); i += 256)
        ((float*)Ps)[i] = 0.f;

    const int u0 = ((tid >> 2) & 3) * 8;
    const int s0 = (tid & 3) * 8;
    const int ksl = tid >> 4;
    float acc[8][8];
#pragma unroll
    for (int i = 0; i < 8; i++)
#pragma unroll
        for (int j = 0; j < 8; j++) acc[i][j] = 0.f;

    for (int kt = 0; kt < K_DIM; kt += TS) {
        __syncthreads();
#pragma unroll
        for (int p = 0; p < 4; p++) {
            int idx = tid + p * 256;
            int rr = idx >> 5;
            int cc = (idx & 31) * 4;
            *(float4*)&qs[rr][cc]  = *(const float4*)(qa  + (t0 + rr) * K_DIM + kt + cc);
            *(float4*)&ks_[rr][cc] = *(const float4*)(kia + (t0 + rr) * K_DIM + kt + cc);
        }
        __syncthreads();
        const int kb = ksl * 8;
#pragma unroll
        for (int km = 0; km < 8; km++) {
            const int kx = kb + km;
            float qv[8], kv[8];
#pragma unroll
            for (int i = 0; i < 8; i++) qv[i] = qs[u0 + i][kx];
#pragma unroll
            for (int j = 0; j < 8; j++) kv[j] = ks_[s0 + j][kx];
#pragma unroll
            for (int i = 0; i < 8; i++)
#pragma unroll
                for (int j = 0; j < 8; j++)
                    acc[i][j] = fmaf(qv[i], kv[j], acc[i][j]);
        }
    }
    __syncthreads();
#pragma unroll
    for (int i = 0; i < 8; i++)
#pragma unroll
        for (int j = 0; j < 8; j++)
            atomicAdd(&Ps[u0 + i][s0 + j], acc[i][j]);
    __syncthreads();

    const int vc = tid * 4;
#pragma unroll
    for (int pass = 0; pass < 4; pass++) {
        float o[8][4];
#pragma unroll
        for (int i = 0; i < 8; i++) { o[i][0] = o[i][1] = o[i][2] = o[i][3] = 0.f; }
        for (int s = 0; s < CHUNK; s++) {
            float4 v4 = *(const float4*)(vv + (t0 + s) * V_DIM + vc);
#pragma unroll
            for (int i = 0; i < 8; i++) {
                const int u = pass * 8 + i;
                float p = (s <= u) ? Ps[u][s] : 0.f;
                o[i][0] = fmaf(p, v4.x, o[i][0]);
                o[i][1] = fmaf(p, v4.y, o[i][1]);
                o[i][2] = fmaf(p, v4.z, o[i][2]);
                o[i][3] = fmaf(p, v4.w, o[i][3]);
            }
        }
#pragma unroll
        for (int i = 0; i < 8; i++) {
            const int u = pass * 8 + i;
            *(float4*)(opre + (t0 + u) * V_DIM + vc) =
                make_float4(o[i][0], o[i][1], o[i][2], o[i][3]);
        }
    }
}

// ---------------- serial v4: double-buffered tensor-core state updates ------
#define SER_DSMEM 54016
__global__ void __launch_bounds__(256, 2) serial_kernel4(
    const __half* __restrict__ khT, const __half* __restrict__ vT,
    const float* __restrict__ a15, __half* __restrict__ snap,
    float* __restrict__ state_out)
{
    extern __shared__ char dyn[];
    __half* khsA[2] = {(__half*)(dyn),         (__half*)(dyn + 20480)};
    __half* vsA[2]  = {(__half*)(dyn + 40960), (__half*)(dyn + 42240)};
    float*  a15A[2] = {(float*)(dyn + 43520),  (float*)(dyn + 44544)};
    __half* snapS   = (__half*)(dyn + 45568);

    const int tid = threadIdx.x;
    const int lane = tid & 31;
    const int wid = tid >> 5;
    const int kg = blockIdx.x & 3;
    const int vsb = blockIdx.x >> 2;
    const int kbaseCTA = kg * 256;
    const int vbase = vsb * 16;

#define SER_PREF(c, b)                                                         \
    {                                                                          \
        const __half* kSrc = khT + ((size_t)(c) * K_DIM + kbaseCTA) * CHUNK;   \
        _Pragma("unroll")                                                      \
        for (int p = 0; p < 4; p++) {                                          \
            const int idx = tid + p * 256;                                     \
            const int row = idx >> 2;                                          \
            const int cc = (idx & 3) * 8;                                      \
            cp_async16(&khsA[b][row * KP + cc], kSrc + row * CHUNK + cc);      \
        }                                                                      \
        if (tid < 64) {                                                        \
            const int row = tid >> 2;                                          \
            const int cc = (tid & 3) * 8;                                      \
            cp_async16(&vsA[b][row * KP + cc],                                 \
                       vT + ((size_t)(c) * V_DIM + vbase + row) * CHUNK + cc); \
        } else if (tid < 128) {                                                \
            const int j = tid - 64;                                            \
            cp_async16_g(&a15A[b][j * 4],                                      \
                         a15 + (size_t)(c) * K_DIM + kbaseCTA + j * 4);        \
        }                                                                      \
        CP_COMMIT();                                                           \
    }

    float acc[2][2][4];
#pragma unroll
    for (int mt = 0; mt < 2; mt++)
#pragma unroll
        for (int nt = 0; nt < 2; nt++)
#pragma unroll
            for (int c = 0; c < 4; c++) acc[mt][nt][c] = 0.f;

    SER_PREF(0, 0);

    for (int cid = 0; cid < NCHUNK; cid++) {
        const int buf = cid & 1;

#pragma unroll
        for (int mt = 0; mt < 2; mt++)
#pragma unroll
            for (int nt = 0; nt < 2; nt++)
#pragma unroll
                for (int h = 0; h < 2; h++) {
                    const int row = wid * 32 + mt * 16 + (lane >> 2) + h * 8;
                    const int col = nt * 8 + (lane & 3) * 2;
                    snapS[col * 264 + row]       = __float2half(acc[mt][nt][2 * h]);
                    snapS[(col + 1) * 264 + row] = __float2half(acc[mt][nt][2 * h + 1]);
                }
        __syncthreads();

        if (cid + 1 < NCHUNK) SER_PREF(cid + 1, buf ^ 1);

        for (int idx = tid; idx < 512; idx += 256) {
            const int vr = idx >> 5;
            const int kc16 = idx & 31;
            uint4 val = *(uint4*)&snapS[vr * 264 + kc16 * 8];
            *(uint4*)(snap + ((size_t)cid * V_DIM + vbase + vr) * K_DIM +
                      kbaseCTA + kc16 * 8) = val;
        }

        if (cid + 1 < NCHUNK) { CP_WAIT(1); } else { CP_WAIT(0); }
        __syncthreads();

#pragma unroll
        for (int mt = 0; mt < 2; mt++)
#pragma unroll
            for (int h = 0; h < 2; h++) {
                const float av = a15A[buf][wid * 32 + mt * 16 + (lane >> 2) + h * 8];
#pragma unroll
                for (int nt = 0; nt < 2; nt++) {
                    acc[mt][nt][2 * h]     *= av;
                    acc[mt][nt][2 * h + 1] *= av;
                }
            }

#pragma unroll
        for (int ks = 0; ks < 2; ks++) {
            const int k0 = ks * 16;
            uint32_t afr[2][4];
            uint32_t bfr[2][2];
#pragma unroll
            for (int mt = 0; mt < 2; mt++) {
                const __half* p = &khsA[buf][(wid * 32 + mt * 16 + (lane & 7) +
                                              ((lane >> 3) & 1) * 8) * KP +
                                             k0 + (lane >> 4) * 8];
                ldm_x4(afr[mt], p);
            }
            {
                uint32_t r[4];
                const __half* p = &vsA[buf][((lane & 7) + (lane >> 4) * 8) * KP +
                                            k0 + ((lane >> 3) & 1) * 8];
                ldm_x4(r, p);
                bfr[0][0] = r[0]; bfr[0][1] = r[1];
                bfr[1][0] = r[2]; bfr[1][1] = r[3];
            }
#pragma unroll
            for (int mt = 0; mt < 2; mt++)
#pragma unroll
                for (int nt = 0; nt < 2; nt++)
                    mma16816(acc[mt][nt], afr[mt], bfr[nt]);
        }
    }
#undef SER_PREF

#pragma unroll
    for (int mt = 0; mt < 2; mt++)
#pragma unroll
        for (int nt = 0; nt < 2; nt++)
#pragma unroll
            for (int h = 0; h < 2; h++) {
                const int row = kbaseCTA + wid * 32 + mt * 16 + (lane >> 2) + h * 8;
                const int col = vbase + nt * 8 + (lane & 3) * 2;
                *(float2*)(state_out + (size_t)row * V_DIM + col) =
                    make_float2(acc[mt][nt][2 * h], acc[mt][nt][2 * h + 1]);
            }
}

// ---------------- inter: opre += qa_chunk @ snapshot^T (mma.sync) -----------
__global__ void __launch_bounds__(256) inter_kernel(
    const __half* __restrict__ qah, const __half* __restrict__ snap,
    float* __restrict__ opre)
{
    __shared__ __half As[2][32 * KP];
    __shared__ __half Bs[2][128 * KP];
    const int tid = threadIdx.x;
    const int lane = tid & 31;
    const int wid = tid >> 5;
    const int warpM = wid >> 2;
    const int warpN = wid & 3;
    const int vt = blockIdx.x;
    const int cid = blockIdx.y + 1;

    const __half* A = qah + (size_t)cid * CHUNK * K_DIM;
    const __half* B = snap + ((size_t)cid * V_DIM + vt * 128) * K_DIM;

    float acc[4][4];
#pragma unroll
    for (int a = 0; a < 4; a++)
#pragma unroll
        for (int c = 0; c < 4; c++) acc[a][c] = 0.f;

#define LOAD_TILE_I(buf, k0)                                                   \
    {                                                                          \
        if (tid < 128) {                                                       \
            const int row = tid >> 2;                                          \
            const int col = (tid & 3) * 8;                                     \
            cp_async16(&As[buf][row * KP + col],                               \
                       A + (size_t)row * K_DIM + (k0) + col);                  \
        }                                                                      \
        _Pragma("unroll")                                                      \
        for (int p = 0; p < 2; p++) {                                          \
            const int c = tid + p * 256;                                       \
            const int row = c >> 2;                                            \
            const int col = (c & 3) * 8;                                       \
            cp_async16(&Bs[buf][row * KP + col],                               \
                       B + (size_t)row * K_DIM + (k0) + col);                  \
        }                                                                      \
    }

    LOAD_TILE_I(0, 0);
    CP_COMMIT();
    const int iters = K_DIM / 32;
    for (int it = 0; it < iters; ++it) {
        if (it + 1 < iters) {
            LOAD_TILE_I((it + 1) & 1, (it + 1) * 32);
            CP_COMMIT();
            CP_WAIT(1);
        } else {
            CP_WAIT(0);
        }
        __syncthreads();
        const __half* Ab = As[it & 1];
        const __half* Bb = Bs[it & 1];
#pragma unroll
        for (int ks = 0; ks < 2; ks++) {
            const int k0 = ks * 16;
            uint32_t afr[4];
            uint32_t bfr[4][2];
            {
                const __half* p = &Ab[(warpM * 16 + (lane & 7) +
                                       ((lane >> 3) & 1) * 8) * KP +
                                      k0 + (lane >> 4) * 8];
                ldm_x4(afr, p);
            }
#pragma unroll
            for (int fp = 0; fp < 2; fp++) {
                uint32_t r[4];
                const __half* p = &Bb[(warpN * 32 + fp * 16 + (lane & 7) +
                                       (lane >> 4) * 8) * KP +
                                      k0 + ((lane >> 3) & 1) * 8];
                ldm_x4(r, p);
                bfr[2 * fp][0] = r[0];     bfr[2 * fp][1] = r[1];
                bfr[2 * fp + 1][0] = r[2]; bfr[2 * fp + 1][1] = r[3];
            }
#pragma unroll
            for (int fn = 0; fn < 4; fn++) mma16816(acc[fn], afr, bfr[fn]);
        }
        __syncthreads();
    }
#undef LOAD_TILE_I

#pragma unroll
    for (int fn = 0; fn < 4; fn++)
#pragma unroll
        for (int h = 0; h < 2; h++) {
            const int row = cid * CHUNK + warpM * 16 + (lane >> 2) + h * 8;
            const int col = vt * 128 + warpN * 32 + fn * 8 + (lane & 3) * 2;
            float2 o = *(float2*)(opre + (size_t)row * V_DIM + col);
            o.x += acc[fn][2 * h];
            o.y += acc[fn][2 * h + 1];
            *(float2*)(opre + (size_t)row * V_DIM + col) = o;
        }
}

// ---------------------------------------------------------------------------
extern "C" void kernel_launch(void* const* d_in, const int* in_sizes, int n_in,
                              void* d_out, int out_size)
{
    const float* X  = (const float*)d_in[0];
    const float* Wq = (const float*)d_in[1];
    const float* bq = (const float*)d_in[2];
    const float* Wk = (const float*)d_in[3];
    const float* bk = (const float*)d_in[4];
    const float* Wv = (const float*)d_in[5];
    const float* bv = (const float*)d_in[6];
    const float* Wg = (const float*)d_in[7];
    const float* bg = (const float*)d_in[8];
    const float* Wo = (const float*)d_in[9];
    const float* bo = (const float*)d_in[10];
    float* out = (float*)d_out;

    float* scratch = 0;
    cudaGetSymbolAddress((void**)&scratch, g_scratch);
    float* qb    = scratch;
    float* kb    = qb   + (size_t)T_DIM * K_DIM;
    float* gb    = kb   + (size_t)T_DIM * K_DIM;
    float* vb    = gb   + (size_t)T_DIM * K_DIM;
    float* qa    = vb   + (size_t)T_DIM * V_DIM;
    float* kia   = qa   + (size_t)T_DIM * K_DIM;
    float* opre  = kia  + (size_t)T_DIM * K_DIM;
    float* a15   = opre + (size_t)T_DIM * V_DIM;
    float* sdump = a15  + (size_t)NCHUNK * K_DIM;

    __half* hscr = 0;
    cudaGetSymbolAddress((void**)&hscr, g_scratch_h);
    __half* Xh    = hscr;
    __half* Wallh = Xh    + (size_t)T_DIM * H_DIM;
    __half* Woh   = Wallh + (size_t)4 * K_DIM * H_DIM;
    __half* opreh = Woh   + (size_t)O_DIM * V_DIM;
    __half* qah   = opreh + (size_t)T_DIM * V_DIM;
    __half* khT   = qah   + (size_t)T_DIM * K_DIM;
    __half* vT    = khT   + (size_t)T_DIM * K_DIM;
    __half* snap  = vT    + (size_t)T_DIM * K_DIM;

    const size_t out_main = (size_t)T_DIM * O_DIM;
    const size_t out_full = out_main + (size_t)K_DIM * V_DIM;
    float* state_out = ((size_t)out_size >= out_full) ? (out + out_main) : sdump;

    // opt-in dynamic smem (host API only; idempotent)
    cudaFuncSetAttribute(gemm_h_nt, cudaFuncAttributeMaxDynamicSharedMemorySize, G_DSMEM);
    cudaFuncSetAttribute(gemm_h_nt_proj, cudaFuncAttributeMaxDynamicSharedMemorySize, G_DSMEM);
    cudaFuncSetAttribute(serial_kernel4, cudaFuncAttributeMaxDynamicSharedMemorySize,
                         SER_DSMEM);

    dim3 blk(256);

    f2h_kernel<<<2048, 256>>>(X, Xh, (int)((size_t)T_DIM * H_DIM / 4));
    f2h4_kernel<<<dim3(512, 4), 256>>>(Wq, Wk, Wg, Wv, Wallh,
                                       (int)((size_t)K_DIM * H_DIM / 4));
    f2h_kernel<<<1024, 256>>>(Wo, Woh, (int)((size_t)O_DIM * V_DIM / 4));

    // merged projection GEMM: CTA 128x256 wide tiles, routed epilogue
    gemm_h_nt_proj<<<dim3(4 * K_DIM / 256, T_DIM / 128), blk, G_DSMEM>>>(
        Xh, Wallh, bq, bk, bg, bv, qb, kb, gb, vb);

    // chunked gated-linear-attention pipeline
    prep_kernel<<<NCHUNK, blk>>>(qb, kb, gb, vb, qa, qah, kia, a15, khT, vT);
    intra_kernel<<<NCHUNK, blk>>>(qa, kia, vb, opre);
    serial_kernel4<<<256, blk, SER_DSMEM>>>(khT, vT, a15, snap, state_out);
    inter_kernel<<<dim3(8, NCHUNK - 1), blk>>>(qah, snap, opre);

    // opre -> fp16, output projection (wide tiles)
    f2h_kernel<<<1024, 256>>>(opre, opreh, (int)((size_t)T_DIM * V_DIM / 4));
    gemm_h_nt<<<dim3(O_DIM / 256, T_DIM / 128), blk, G_DSMEM>>>(opreh, Woh, bo, out,
                                                                T_DIM, O_DIM, V_DIM, 0);
}

// round 15
// speedup vs baseline: 1.1483x; 1.1483x over previous
#include <cuda_runtime.h>
#include <cuda_fp16.h>
#include <math.h>
#include <stddef.h>
#include <stdint.h>

typedef unsigned long long ull;

#define T_DIM 4096
#define H_DIM 2048
#define K_DIM 1024
#define V_DIM 1024
#define O_DIM 2048
#define CHUNK 32
#define NCHUNK 128

// fp32 scratch: q | k | g | v | qa | kia | opre | a15 | sdump
__device__ __align__(16) float g_scratch[(size_t)5 * T_DIM * K_DIM +
                                         (size_t)2 * T_DIM * V_DIM +
                                         (size_t)NCHUNK * K_DIM +
                                         (size_t)K_DIM * V_DIM];
// fp16 scratch: Xh | Wall | Woh | opreh | qah | khT | vT | snap
__device__ __align__(16) __half g_scratch_h[(size_t)T_DIM * H_DIM +
                                            (size_t)4 * K_DIM * H_DIM +
                                            (size_t)O_DIM * V_DIM +
                                            (size_t)T_DIM * V_DIM +
                                            (size_t)3 * T_DIM * K_DIM +
                                            (size_t)NCHUNK * K_DIM * V_DIM];

// ---------------- helpers ----------------
__device__ __forceinline__ uint32_t smem_u32(const void* p) {
    return (uint32_t)__cvta_generic_to_shared(p);
}
__device__ __forceinline__ void ldm_x4(uint32_t* r, const __half* p) {
    uint32_t addr = smem_u32(p);
    asm volatile("ldmatrix.sync.aligned.m8n8.x4.shared.b16 {%0,%1,%2,%3}, [%4];"
                 : "=r"(r[0]), "=r"(r[1]), "=r"(r[2]), "=r"(r[3]) : "r"(addr));
}
__device__ __forceinline__ void mma16816(float* d, const uint32_t* a, const uint32_t* b) {
    asm volatile(
        "mma.sync.aligned.m16n8k16.row.col.f32.f16.f16.f32 "
        "{%0,%1,%2,%3}, {%4,%5,%6,%7}, {%8,%9}, {%0,%1,%2,%3};"
        : "+f"(d[0]), "+f"(d[1]), "+f"(d[2]), "+f"(d[3])
        : "r"(a[0]), "r"(a[1]), "r"(a[2]), "r"(a[3]), "r"(b[0]), "r"(b[1]));
}
__device__ __forceinline__ void cp_async16(__half* smem_dst, const __half* gsrc) {
    asm volatile("cp.async.cg.shared.global [%0], [%1], 16;"
                 :: "r"(smem_u32(smem_dst)), "l"(gsrc));
}
__device__ __forceinline__ void cp_async16_g(void* smem_dst, const void* gsrc) {
    asm volatile("cp.async.cg.shared.global [%0], [%1], 16;"
                 :: "r"(smem_u32(smem_dst)), "l"(gsrc));
}
#define CP_COMMIT() asm volatile("cp.async.commit_group;")
#define CP_WAIT(n)  asm volatile("cp.async.wait_group %0;" :: "n"(n))

// ---------------- fp32 -> fp16 convert (single + batched x4) ----------------
__global__ void f2h_kernel(const float* __restrict__ src, __half* __restrict__ dst, int n4)
{
    int i = blockIdx.x * blockDim.x + threadIdx.x;
    const int stride = gridDim.x * blockDim.x;
    for (; i < n4; i += stride) {
        float4 v = ((const float4*)src)[i];
        __half2 h0 = __floats2half2_rn(v.x, v.y);
        __half2 h1 = __floats2half2_rn(v.z, v.w);
        uint2 u;
        u.x = *reinterpret_cast<unsigned*>(&h0);
        u.y = *reinterpret_cast<unsigned*>(&h1);
        ((uint2*)dst)[i] = u;
    }
}
__global__ void f2h4_kernel(const float* __restrict__ s0, const float* __restrict__ s1,
                            const float* __restrict__ s2, const float* __restrict__ s3,
                            __half* __restrict__ dst, int n4)
{
    const float* src = (blockIdx.y == 0) ? s0 : (blockIdx.y == 1) ? s1
                       : (blockIdx.y == 2) ? s2 : s3;
    __half* d = dst + (size_t)blockIdx.y * (size_t)n4 * 4;
    int i = blockIdx.x * blockDim.x + threadIdx.x;
    const int stride = gridDim.x * blockDim.x;
    for (; i < n4; i += stride) {
        float4 v = ((const float4*)src)[i];
        __half2 h0 = __floats2half2_rn(v.x, v.y);
        __half2 h1 = __floats2half2_rn(v.z, v.w);
        uint2 u;
        u.x = *reinterpret_cast<unsigned*>(&h0);
        u.y = *reinterpret_cast<unsigned*>(&h1);
        ((uint2*)d)[i] = u;
    }
}

// ---------------- fp16 NT GEMM: 128x128 tile, warp 64x32, 3-stage pipeline --
// R13 config (2 CTAs/SM, proven) but with THREE cp.async stages so the
// mainloop needs only ONE __syncthreads per iteration (load for it+2 targets
// a third buffer; its readers all passed this iteration's barrier).
#define KP 40
#define G3_STAGE (128 * KP)            // halves per matrix per stage
#define G3_DSMEM (6 * G3_STAGE * 2)    // 3 stages x (As+Bs) = 61440 B

struct EpiPlain {
    const float* bias; float* C; int N; int act;
    __device__ __forceinline__ void store(int row, int col, float c0, float c1) const {
        c0 += __ldg(&bias[col]); c1 += __ldg(&bias[col + 1]);
        if (act) { c0 = 1.f / (1.f + expf(-c0)); c1 = 1.f / (1.f + expf(-c1)); }
        *(float2*)(C + (size_t)row * N + col) = make_float2(c0, c1);
    }
};
// routed epilogue: col>>10 selects one of 4 outputs (k,g get sigmoid)
struct EpiRoute {
    const float* b0; const float* b1; const float* b2; const float* b3;
    float* d0; float* d1; float* d2; float* d3;
    __device__ __forceinline__ void store(int row, int col, float c0, float c1) const {
        const int sel = col >> 10;
        const int lc = col & 1023;
        const float* bias = (sel == 0) ? b0 : (sel == 1) ? b1 : (sel == 2) ? b2 : b3;
        float* C = (sel == 0) ? d0 : (sel == 1) ? d1 : (sel == 2) ? d2 : d3;
        c0 += __ldg(&bias[lc]); c1 += __ldg(&bias[lc + 1]);
        if (sel == 1 || sel == 2) {
            c0 = 1.f / (1.f + expf(-c0)); c1 = 1.f / (1.f + expf(-c1));
        }
        *(float2*)(C + (size_t)row * 1024 + lc) = make_float2(c0, c1);
    }
};

template <class Epi>
__device__ __forceinline__ void gemm_body(
    const __half* __restrict__ A, const __half* __restrict__ B,
    int Kd, int bm, int bn, const Epi& epi)
{
    extern __shared__ __half gsm[];
    // stage s: As at gsm + s*G3_STAGE, Bs at gsm + 3*G3_STAGE + s*G3_STAGE
    const int tid = threadIdx.x;
    const int lane = tid & 31;
    const int wid = tid >> 5;
    const int warpM = wid >> 2;
    const int warpN = wid & 3;

    float acc[4][4][4];
#pragma unroll
    for (int a = 0; a < 4; a++)
#pragma unroll
        for (int b = 0; b < 4; b++)
#pragma unroll
            for (int c = 0; c < 4; c++) acc[a][b][c] = 0.f;

    const int iters = Kd / 32;

#define LOAD_TILE3(stg, k0)                                                    \
    {                                                                          \
        __half* Asb = gsm + (stg) * G3_STAGE;                                  \
        __half* Bsb = gsm + (3 + (stg)) * G3_STAGE;                            \
        _Pragma("unroll")                                                      \
        for (int p = 0; p < 2; p++) {                                          \
            const int c = tid + p * 256;                                       \
            const int row = c >> 2;                                            \
            const int col = (c & 3) * 8;                                       \
            cp_async16(&Asb[row * KP + col],                                   \
                       A + (size_t)(bm + row) * Kd + (k0) + col);              \
            cp_async16(&Bsb[row * KP + col],                                   \
                       B + (size_t)(bn + row) * Kd + (k0) + col);              \
        }                                                                      \
    }

    LOAD_TILE3(0, 0);  CP_COMMIT();
    LOAD_TILE3(1, 32); CP_COMMIT();

    for (int it = 0; it < iters; ++it) {
        if (it + 1 < iters) { CP_WAIT(1); } else { CP_WAIT(0); }
        __syncthreads();   // tile it visible to all; prev iter's readers done

        if (it + 2 < iters) {
            LOAD_TILE3((it + 2) % 3, (it + 2) * 32);
            CP_COMMIT();
        }

        const __half* Ab = gsm + (it % 3) * G3_STAGE;
        const __half* Bb = gsm + (3 + (it % 3)) * G3_STAGE;
#pragma unroll
        for (int ks = 0; ks < 2; ks++) {
            const int k0 = ks * 16;
            uint32_t afr[4][4];
            uint32_t bfr[4][2];
#pragma unroll
            for (int fm = 0; fm < 4; fm++) {
                const __half* p = &Ab[(warpM * 64 + fm * 16 + (lane & 7) +
                                       ((lane >> 3) & 1) * 8) * KP +
                                      k0 + (lane >> 4) * 8];
                ldm_x4(afr[fm], p);
            }
#pragma unroll
            for (int fp = 0; fp < 2; fp++) {
                uint32_t r[4];
                const __half* p = &Bb[(warpN * 32 + fp * 16 + (lane & 7) +
                                       (lane >> 4) * 8) * KP +
                                      k0 + ((lane >> 3) & 1) * 8];
                ldm_x4(r, p);
                bfr[2 * fp][0] = r[0];     bfr[2 * fp][1] = r[1];
                bfr[2 * fp + 1][0] = r[2]; bfr[2 * fp + 1][1] = r[3];
            }
#pragma unroll
            for (int fm = 0; fm < 4; fm++)
#pragma unroll
                for (int fn = 0; fn < 4; fn++)
                    mma16816(acc[fm][fn], afr[fm], bfr[fn]);
        }
    }
#undef LOAD_TILE3

#pragma unroll
    for (int fm = 0; fm < 4; fm++)
#pragma unroll
        for (int fn = 0; fn < 4; fn++)
#pragma unroll
            for (int h = 0; h < 2; h++) {
                const int row = bm + warpM * 64 + fm * 16 + (lane >> 2) + h * 8;
                const int col = bn + warpN * 32 + fn * 8 + (lane & 3) * 2;
                epi.store(row, col, acc[fm][fn][2 * h], acc[fm][fn][2 * h + 1]);
            }
}

__global__ void __launch_bounds__(256, 2) gemm_h_nt(
    const __half* __restrict__ A, const __half* __restrict__ B,
    const float* __restrict__ bias, float* __restrict__ C,
    int M, int N, int Kd, int act)
{
    EpiPlain epi{bias, C, N, act};
    gemm_body(A, B, Kd, blockIdx.y * 128, blockIdx.x * 128, epi);
}

// merged 4-projection GEMM: B = stacked [Wq;Wk;Wg;Wv] (4096 x 2048), routed epi
__global__ void __launch_bounds__(256, 2) gemm_h_nt_proj(
    const __half* __restrict__ A, const __half* __restrict__ Wall,
    const float* bq, const float* bk, const float* bg, const float* bv,
    float* qb, float* kb, float* gb, float* vb)
{
    EpiRoute epi{bq, bk, bg, bv, qb, kb, gb, vb};
    gemm_body(A, Wall, H_DIM, blockIdx.y * 128, blockIdx.x * 128, epi);
}

// ---------------- prep: per-chunk cumulative gates ----------------
__global__ void __launch_bounds__(256) prep_kernel(
    const float* __restrict__ q, const float* __restrict__ kk,
    const float* __restrict__ g, const float* __restrict__ vv,
    float* __restrict__ qa, __half* __restrict__ qah,
    float* __restrict__ kia, float* __restrict__ a15,
    __half* __restrict__ khT, __half* __restrict__ vT)
{
    const int cid = blockIdx.x;
    const int kc = threadIdx.x * 4;
    const size_t t0 = (size_t)cid * CHUNK;
    float4 A = make_float4(1.f, 1.f, 1.f, 1.f);
#pragma unroll 4
    for (int u = 0; u < CHUNK; u++) {
        const size_t off = (t0 + u) * K_DIM + kc;
        float4 gv = *(const float4*)(g + off);
        A.x *= gv.x; A.y *= gv.y; A.z *= gv.z; A.w *= gv.w;
        float4 qv = *(const float4*)(q + off);
        float4 qa4 = make_float4(qv.x * A.x, qv.y * A.y, qv.z * A.z, qv.w * A.w);
        *(float4*)(qa + off) = qa4;
        __half2 h0 = __floats2half2_rn(qa4.x, qa4.y);
        __half2 h1 = __floats2half2_rn(qa4.z, qa4.w);
        uint2 uu; uu.x = *(unsigned*)&h0; uu.y = *(unsigned*)&h1;
        *(uint2*)(qah + off) = uu;
        float4 kv = *(const float4*)(kk + off);
        float4 ki = make_float4(__fdiv_rn(kv.x, A.x), __fdiv_rn(kv.y, A.y),
                                __fdiv_rn(kv.z, A.z), __fdiv_rn(kv.w, A.w));
        *(float4*)(kia + off) = ki;
    }
    *(float4*)(a15 + (size_t)cid * K_DIM + kc) = A;

    {
        uint32_t buf[4][16];
        float prev[4];
#pragma unroll
        for (int u = 0; u < CHUNK; u++) {
            const size_t off = (t0 + u) * K_DIM + kc;
            float4 ki = *(const float4*)(kia + off);
            float cur[4] = {ki.x * A.x, ki.y * A.y, ki.z * A.z, ki.w * A.w};
            if (u & 1) {
#pragma unroll
                for (int j = 0; j < 4; j++) {
                    __half2 h = __floats2half2_rn(prev[j], cur[j]);
                    buf[j][u >> 1] = *(unsigned*)&h;
                }
            } else {
#pragma unroll
                for (int j = 0; j < 4; j++) prev[j] = cur[j];
            }
        }
#pragma unroll
        for (int j = 0; j < 4; j++) {
            __half* dst = khT + ((size_t)cid * K_DIM + kc + j) * CHUNK;
#pragma unroll
            for (int c = 0; c < 4; c++)
                *(uint4*)(dst + c * 8) = *(uint4*)&buf[j][c * 4];
        }
    }
    {
        uint32_t buf[4][16];
        float prev[4];
#pragma unroll
        for (int u = 0; u < CHUNK; u++) {
            float4 v4 = *(const float4*)(vv + (t0 + u) * V_DIM + kc);
            float cur[4] = {v4.x, v4.y, v4.z, v4.w};
            if (u & 1) {
#pragma unroll
                for (int j = 0; j < 4; j++) {
                    __half2 h = __floats2half2_rn(prev[j], cur[j]);
                    buf[j][u >> 1] = *(unsigned*)&h;
                }
            } else {
#pragma unroll
                for (int j = 0; j < 4; j++) prev[j] = cur[j];
            }
        }
#pragma unroll
        for (int j = 0; j < 4; j++) {
            __half* dst = vT + ((size_t)cid * V_DIM + kc + j) * CHUNK;
#pragma unroll
            for (int c = 0; c < 4; c++)
                *(uint4*)(dst + c * 8) = *(uint4*)&buf[j][c * 4];
        }
    }
}

// ---------------- intra-chunk: P = QA @ KIA^T (masked), out = P @ V ----------
#define TS 128
__global__ void __launch_bounds__(256) intra_kernel(
    const float* __restrict__ qa, const float* __restrict__ kia,
    const float* __restrict__ vv, float* __restrict__ opre)
{
    __shared__ float qs[CHUNK][TS + 4];
    __shared__ float ks_[CHUNK][TS + 4];
    __shared__ float Ps[CHUNK][CHUNK + 1];
    const int tid = threadIdx.x;
    const int cid = blockIdx.x;
    const size_t t0 = (size_t)cid * CHUNK;

    for (int i = tid; i < CHUNK * (CHUNK + 1); i += 256)
        ((float*)Ps)[i] = 0.f;

    const int u0 = ((tid >> 2) & 3) * 8;
    const int s0 = (tid & 3) * 8;
    const int ksl = tid >> 4;
    float acc[8][8];
#pragma unroll
    for (int i = 0; i < 8; i++)
#pragma unroll
        for (int j = 0; j < 8; j++) acc[i][j] = 0.f;

    for (int kt = 0; kt < K_DIM; kt += TS) {
        __syncthreads();
#pragma unroll
        for (int p = 0; p < 4; p++) {
            int idx = tid + p * 256;
            int rr = idx >> 5;
            int cc = (idx & 31) * 4;
            *(float4*)&qs[rr][cc]  = *(const float4*)(qa  + (t0 + rr) * K_DIM + kt + cc);
            *(float4*)&ks_[rr][cc] = *(const float4*)(kia + (t0 + rr) * K_DIM + kt + cc);
        }
        __syncthreads();
        const int kb = ksl * 8;
#pragma unroll
        for (int km = 0; km < 8; km++) {
            const int kx = kb + km;
            float qv[8], kv[8];
#pragma unroll
            for (int i = 0; i < 8; i++) qv[i] = qs[u0 + i][kx];
#pragma unroll
            for (int j = 0; j < 8; j++) kv[j] = ks_[s0 + j][kx];
#pragma unroll
            for (int i = 0; i < 8; i++)
#pragma unroll
                for (int j = 0; j < 8; j++)
                    acc[i][j] = fmaf(qv[i], kv[j], acc[i][j]);
        }
    }
    __syncthreads();
#pragma unroll
    for (int i = 0; i < 8; i++)
#pragma unroll
        for (int j = 0; j < 8; j++)
            atomicAdd(&Ps[u0 + i][s0 + j], acc[i][j]);
    __syncthreads();

    const int vc = tid * 4;
#pragma unroll
    for (int pass = 0; pass < 4; pass++) {
        float o[8][4];
#pragma unroll
        for (int i = 0; i < 8; i++) { o[i][0] = o[i][1] = o[i][2] = o[i][3] = 0.f; }
        for (int s = 0; s < CHUNK; s++) {
            float4 v4 = *(const float4*)(vv + (t0 + s) * V_DIM + vc);
#pragma unroll
            for (int i = 0; i < 8; i++) {
                const int u = pass * 8 + i;
                float p = (s <= u) ? Ps[u][s] : 0.f;
                o[i][0] = fmaf(p, v4.x, o[i][0]);
                o[i][1] = fmaf(p, v4.y, o[i][1]);
                o[i][2] = fmaf(p, v4.z, o[i][2]);
                o[i][3] = fmaf(p, v4.w, o[i][3]);
            }
        }
#pragma unroll
        for (int i = 0; i < 8; i++) {
            const int u = pass * 8 + i;
            *(float4*)(opre + (t0 + u) * V_DIM + vc) =
                make_float4(o[i][0], o[i][1], o[i][2], o[i][3]);
        }
    }
}

// ---------------- serial v4: double-buffered tensor-core state updates ------
#define SER_DSMEM 54016
__global__ void __launch_bounds__(256, 2) serial_kernel4(
    const __half* __restrict__ khT, const __half* __restrict__ vT,
    const float* __restrict__ a15, __half* __restrict__ snap,
    float* __restrict__ state_out)
{
    extern __shared__ char dyn[];
    __half* khsA[2] = {(__half*)(dyn),         (__half*)(dyn + 20480)};
    __half* vsA[2]  = {(__half*)(dyn + 40960), (__half*)(dyn + 42240)};
    float*  a15A[2] = {(float*)(dyn + 43520),  (float*)(dyn + 44544)};
    __half* snapS   = (__half*)(dyn + 45568);

    const int tid = threadIdx.x;
    const int lane = tid & 31;
    const int wid = tid >> 5;
    const int kg = blockIdx.x & 3;
    const int vsb = blockIdx.x >> 2;
    const int kbaseCTA = kg * 256;
    const int vbase = vsb * 16;

#define SER_PREF(c, b)                                                         \
    {                                                                          \
        const __half* kSrc = khT + ((size_t)(c) * K_DIM + kbaseCTA) * CHUNK;   \
        _Pragma("unroll")                                                      \
        for (int p = 0; p < 4; p++) {                                          \
            const int idx = tid + p * 256;                                     \
            const int row = idx >> 2;                                          \
            const int cc = (idx & 3) * 8;                                      \
            cp_async16(&khsA[b][row * KP + cc], kSrc + row * CHUNK + cc);      \
        }                                                                      \
        if (tid < 64) {                                                        \
            const int row = tid >> 2;                                          \
            const int cc = (tid & 3) * 8;                                      \
            cp_async16(&vsA[b][row * KP + cc],                                 \
                       vT + ((size_t)(c) * V_DIM + vbase + row) * CHUNK + cc); \
        } else if (tid < 128) {                                                \
            const int j = tid - 64;                                            \
            cp_async16_g(&a15A[b][j * 4],                                      \
                         a15 + (size_t)(c) * K_DIM + kbaseCTA + j * 4);        \
        }                                                                      \
        CP_COMMIT();                                                           \
    }

    float acc[2][2][4];
#pragma unroll
    for (int mt = 0; mt < 2; mt++)
#pragma unroll
        for (int nt = 0; nt < 2; nt++)
#pragma unroll
            for (int c = 0; c < 4; c++) acc[mt][nt][c] = 0.f;

    SER_PREF(0, 0);

    for (int cid = 0; cid < NCHUNK; cid++) {
        const int buf = cid & 1;

#pragma unroll
        for (int mt = 0; mt < 2; mt++)
#pragma unroll
            for (int nt = 0; nt < 2; nt++)
#pragma unroll
                for (int h = 0; h < 2; h++) {
                    const int row = wid * 32 + mt * 16 + (lane >> 2) + h * 8;
                    const int col = nt * 8 + (lane & 3) * 2;
                    snapS[col * 264 + row]       = __float2half(acc[mt][nt][2 * h]);
                    snapS[(col + 1) * 264 + row] = __float2half(acc[mt][nt][2 * h + 1]);
                }
        __syncthreads();

        if (cid + 1 < NCHUNK) SER_PREF(cid + 1, buf ^ 1);

        for (int idx = tid; idx < 512; idx += 256) {
            const int vr = idx >> 5;
            const int kc16 = idx & 31;
            uint4 val = *(uint4*)&snapS[vr * 264 + kc16 * 8];
            *(uint4*)(snap + ((size_t)cid * V_DIM + vbase + vr) * K_DIM +
                      kbaseCTA + kc16 * 8) = val;
        }

        if (cid + 1 < NCHUNK) { CP_WAIT(1); } else { CP_WAIT(0); }
        __syncthreads();

#pragma unroll
        for (int mt = 0; mt < 2; mt++)
#pragma unroll
            for (int h = 0; h < 2; h++) {
                const float av = a15A[buf][wid * 32 + mt * 16 + (lane >> 2) + h * 8];
#pragma unroll
                for (int nt = 0; nt < 2; nt++) {
                    acc[mt][nt][2 * h]     *= av;
                    acc[mt][nt][2 * h + 1] *= av;
                }
            }

#pragma unroll
        for (int ks = 0; ks < 2; ks++) {
            const int k0 = ks * 16;
            uint32_t afr[2][4];
            uint32_t bfr[2][2];
#pragma unroll
            for (int mt = 0; mt < 2; mt++) {
                const __half* p = &khsA[buf][(wid * 32 + mt * 16 + (lane & 7) +
                                              ((lane >> 3) & 1) * 8) * KP +
                                             k0 + (lane >> 4) * 8];
                ldm_x4(afr[mt], p);
            }
            {
                uint32_t r[4];
                const __half* p = &vsA[buf][((lane & 7) + (lane >> 4) * 8) * KP +
                                            k0 + ((lane >> 3) & 1) * 8];
                ldm_x4(r, p);
                bfr[0][0] = r[0]; bfr[0][1] = r[1];
                bfr[1][0] = r[2]; bfr[1][1] = r[3];
            }
#pragma unroll
            for (int mt = 0; mt < 2; mt++)
#pragma unroll
                for (int nt = 0; nt < 2; nt++)
                    mma16816(acc[mt][nt], afr[mt], bfr[nt]);
        }
    }
#undef SER_PREF

#pragma unroll
    for (int mt = 0; mt < 2; mt++)
#pragma unroll
        for (int nt = 0; nt < 2; nt++)
#pragma unroll
            for (int h = 0; h < 2; h++) {
                const int row = kbaseCTA + wid * 32 + mt * 16 + (lane >> 2) + h * 8;
                const int col = vbase + nt * 8 + (lane & 3) * 2;
                *(float2*)(state_out + (size_t)row * V_DIM + col) =
                    make_float2(acc[mt][nt][2 * h], acc[mt][nt][2 * h + 1]);
            }
}

// ---------------- inter: opre += qa_chunk @ snapshot^T (mma.sync) -----------
__global__ void __launch_bounds__(256) inter_kernel(
    const __half* __restrict__ qah, const __half* __restrict__ snap,
    float* __restrict__ opre)
{
    __shared__ __half As[2][32 * KP];
    __shared__ __half Bs[2][128 * KP];
    const int tid = threadIdx.x;
    const int lane = tid & 31;
    const int wid = tid >> 5;
    const int warpM = wid >> 2;
    const int warpN = wid & 3;
    const int vt = blockIdx.x;
    const int cid = blockIdx.y + 1;

    const __half* A = qah + (size_t)cid * CHUNK * K_DIM;
    const __half* B = snap + ((size_t)cid * V_DIM + vt * 128) * K_DIM;

    float acc[4][4];
#pragma unroll
    for (int a = 0; a < 4; a++)
#pragma unroll
        for (int c = 0; c < 4; c++) acc[a][c] = 0.f;

#define LOAD_TILE_I(buf, k0)                                                   \
    {                                                                          \
        if (tid < 128) {                                                       \
            const int row = tid >> 2;                                          \
            const int col = (tid & 3) * 8;                                     \
            cp_async16(&As[buf][row * KP + col],                               \
                       A + (size_t)row * K_DIM + (k0) + col);                  \
        }                                                                      \
        _Pragma("unroll")                                                      \
        for (int p = 0; p < 2; p++) {                                          \
            const int c = tid + p * 256;                                       \
            const int row = c >> 2;                                            \
            const int col = (c & 3) * 8;                                       \
            cp_async16(&Bs[buf][row * KP + col],                               \
                       B + (size_t)row * K_DIM + (k0) + col);                  \
        }                                                                      \
    }

    LOAD_TILE_I(0, 0);
    CP_COMMIT();
    const int iters = K_DIM / 32;
    for (int it = 0; it < iters; ++it) {
        if (it + 1 < iters) {
            LOAD_TILE_I((it + 1) & 1, (it + 1) * 32);
            CP_COMMIT();
            CP_WAIT(1);
        } else {
            CP_WAIT(0);
        }
        __syncthreads();
        const __half* Ab = As[it & 1];
        const __half* Bb = Bs[it & 1];
#pragma unroll
        for (int ks = 0; ks < 2; ks++) {
            const int k0 = ks * 16;
            uint32_t afr[4];
            uint32_t bfr[4][2];
            {
                const __half* p = &Ab[(warpM * 16 + (lane & 7) +
                                       ((lane >> 3) & 1) * 8) * KP +
                                      k0 + (lane >> 4) * 8];
                ldm_x4(afr, p);
            }
#pragma unroll
            for (int fp = 0; fp < 2; fp++) {
                uint32_t r[4];
                const __half* p = &Bb[(warpN * 32 + fp * 16 + (lane & 7) +
                                       (lane >> 4) * 8) * KP +
                                      k0 + ((lane >> 3) & 1) * 8];
                ldm_x4(r, p);
                bfr[2 * fp][0] = r[0];     bfr[2 * fp][1] = r[1];
                bfr[2 * fp + 1][0] = r[2]; bfr[2 * fp + 1][1] = r[3];
            }
#pragma unroll
            for (int fn = 0; fn < 4; fn++) mma16816(acc[fn], afr, bfr[fn]);
        }
        __syncthreads();
    }
#undef LOAD_TILE_I

#pragma unroll
    for (int fn = 0; fn < 4; fn++)
#pragma unroll
        for (int h = 0; h < 2; h++) {
            const int row = cid * CHUNK + warpM * 16 + (lane >> 2) + h * 8;
            const int col = vt * 128 + warpN * 32 + fn * 8 + (lane & 3) * 2;
            float2 o = *(float2*)(opre + (size_t)row * V_DIM + col);
            o.x += acc[fn][2 * h];
            o.y += acc[fn][2 * h + 1];
            *(float2*)(opre + (size_t)row * V_DIM + col) = o;
        }
}

// ---------------------------------------------------------------------------
extern "C" void kernel_launch(void* const* d_in, const int* in_sizes, int n_in,
                              void* d_out, int out_size)
{
    const float* X  = (const float*)d_in[0];
    const float* Wq = (const float*)d_in[1];
    const float* bq = (const float*)d_in[2];
    const float* Wk = (const float*)d_in[3];
    const float* bk = (const float*)d_in[4];
    const float* Wv = (const float*)d_in[5];
    const float* bv = (const float*)d_in[6];
    const float* Wg = (const float*)d_in[7];
    const float* bg = (const float*)d_in[8];
    const float* Wo = (const float*)d_in[9];
    const float* bo = (const float*)d_in[10];
    float* out = (float*)d_out;

    float* scratch = 0;
    cudaGetSymbolAddress((void**)&scratch, g_scratch);
    float* qb    = scratch;
    float* kb    = qb   + (size_t)T_DIM * K_DIM;
    float* gb    = kb   + (size_t)T_DIM * K_DIM;
    float* vb    = gb   + (size_t)T_DIM * K_DIM;
    float* qa    = vb   + (size_t)T_DIM * V_DIM;
    float* kia   = qa   + (size_t)T_DIM * K_DIM;
    float* opre  = kia  + (size_t)T_DIM * K_DIM;
    float* a15   = opre + (size_t)T_DIM * V_DIM;
    float* sdump = a15  + (size_t)NCHUNK * K_DIM;

    __half* hscr = 0;
    cudaGetSymbolAddress((void**)&hscr, g_scratch_h);
    __half* Xh    = hscr;
    __half* Wallh = Xh    + (size_t)T_DIM * H_DIM;
    __half* Woh   = Wallh + (size_t)4 * K_DIM * H_DIM;
    __half* opreh = Woh   + (size_t)O_DIM * V_DIM;
    __half* qah   = opreh + (size_t)T_DIM * V_DIM;
    __half* khT   = qah   + (size_t)T_DIM * K_DIM;
    __half* vT    = khT   + (size_t)T_DIM * K_DIM;
    __half* snap  = vT    + (size_t)T_DIM * K_DIM;

    const size_t out_main = (size_t)T_DIM * O_DIM;
    const size_t out_full = out_main + (size_t)K_DIM * V_DIM;
    float* state_out = ((size_t)out_size >= out_full) ? (out + out_main) : sdump;

    // opt-in dynamic smem (host API only; idempotent)
    cudaFuncSetAttribute(gemm_h_nt, cudaFuncAttributeMaxDynamicSharedMemorySize, G3_DSMEM);
    cudaFuncSetAttribute(gemm_h_nt_proj, cudaFuncAttributeMaxDynamicSharedMemorySize, G3_DSMEM);
    cudaFuncSetAttribute(serial_kernel4, cudaFuncAttributeMaxDynamicSharedMemorySize,
                         SER_DSMEM);

    dim3 blk(256);

    f2h_kernel<<<2048, 256>>>(X, Xh, (int)((size_t)T_DIM * H_DIM / 4));
    f2h4_kernel<<<dim3(512, 4), 256>>>(Wq, Wk, Wg, Wv, Wallh,
                                       (int)((size_t)K_DIM * H_DIM / 4));
    f2h_kernel<<<1024, 256>>>(Wo, Woh, (int)((size_t)O_DIM * V_DIM / 4));

    // merged projection GEMM: 3-stage pipeline, one barrier per iteration
    gemm_h_nt_proj<<<dim3(4 * K_DIM / 128, T_DIM / 128), blk, G3_DSMEM>>>(
        Xh, Wallh, bq, bk, bg, bv, qb, kb, gb, vb);

    // chunked gated-linear-attention pipeline
    prep_kernel<<<NCHUNK, blk>>>(qb, kb, gb, vb, qa, qah, kia, a15, khT, vT);
    intra_kernel<<<NCHUNK, blk>>>(qa, kia, vb, opre);
    serial_kernel4<<<256, blk, SER_DSMEM>>>(khT, vT, a15, snap, state_out);
    inter_kernel<<<dim3(8, NCHUNK - 1), blk>>>(qah, snap, opre);

    // opre -> fp16, output projection
    f2h_kernel<<<1024, 256>>>(opre, opreh, (int)((size_t)T_DIM * V_DIM / 4));
    gemm_h_nt<<<dim3(O_DIM / 128, T_DIM / 128), blk, G3_DSMEM>>>(opreh, Woh, bo, out,
                                                                 T_DIM, O_DIM, V_DIM, 0);
}

// round 17
// speedup vs baseline: 1.2147x; 1.0578x over previous
#include <cuda_runtime.h>
#include <cuda_fp16.h>
#include <math.h>
#include <stddef.h>
#include <stdint.h>

typedef unsigned long long ull;

#define T_DIM 4096
#define H_DIM 2048
#define K_DIM 1024
#define V_DIM 1024
#define O_DIM 2048
#define CHUNK 32
#define NCHUNK 128

// fp32 scratch: q | k | g | v | qa | kia | opre | a15 | sdump
__device__ __align__(16) float g_scratch[(size_t)5 * T_DIM * K_DIM +
                                         (size_t)2 * T_DIM * V_DIM +
                                         (size_t)NCHUNK * K_DIM +
                                         (size_t)K_DIM * V_DIM];
// fp16 scratch: Xh | Wall | Woh | opreh | qah | khT | vT | snap
__device__ __align__(16) __half g_scratch_h[(size_t)T_DIM * H_DIM +
                                            (size_t)4 * K_DIM * H_DIM +
                                            (size_t)O_DIM * V_DIM +
                                            (size_t)T_DIM * V_DIM +
                                            (size_t)3 * T_DIM * K_DIM +
                                            (size_t)NCHUNK * K_DIM * V_DIM];

// ---------------- helpers ----------------
__device__ __forceinline__ uint32_t smem_u32(const void* p) {
    return (uint32_t)__cvta_generic_to_shared(p);
}
__device__ __forceinline__ void ldm_x4(uint32_t* r, const __half* p) {
    uint32_t addr = smem_u32(p);
    asm volatile("ldmatrix.sync.aligned.m8n8.x4.shared.b16 {%0,%1,%2,%3}, [%4];"
                 : "=r"(r[0]), "=r"(r[1]), "=r"(r[2]), "=r"(r[3]) : "r"(addr));
}
__device__ __forceinline__ void mma16816(float* d, const uint32_t* a, const uint32_t* b) {
    asm volatile(
        "mma.sync.aligned.m16n8k16.row.col.f32.f16.f16.f32 "
        "{%0,%1,%2,%3}, {%4,%5,%6,%7}, {%8,%9}, {%0,%1,%2,%3};"
        : "+f"(d[0]), "+f"(d[1]), "+f"(d[2]), "+f"(d[3])
        : "r"(a[0]), "r"(a[1]), "r"(a[2]), "r"(a[3]), "r"(b[0]), "r"(b[1]));
}
__device__ __forceinline__ void cp_async16(__half* smem_dst, const __half* gsrc) {
    asm volatile("cp.async.cg.shared.global [%0], [%1], 16;"
                 :: "r"(smem_u32(smem_dst)), "l"(gsrc));
}
__device__ __forceinline__ void cp_async16_g(void* smem_dst, const void* gsrc) {
    asm volatile("cp.async.cg.shared.global [%0], [%1], 16;"
                 :: "r"(smem_u32(smem_dst)), "l"(gsrc));
}
#define CP_COMMIT() asm volatile("cp.async.commit_group;")
#define CP_WAIT(n)  asm volatile("cp.async.wait_group %0;" :: "n"(n))

// ---------------- fp32 -> fp16 convert (single + batched x5) ----------------
__global__ void f2h_kernel(const float* __restrict__ src, __half* __restrict__ dst, int n4)
{
    int i = blockIdx.x * blockDim.x + threadIdx.x;
    const int stride = gridDim.x * blockDim.x;
    for (; i < n4; i += stride) {
        float4 v = ((const float4*)src)[i];
        __half2 h0 = __floats2half2_rn(v.x, v.y);
        __half2 h1 = __floats2half2_rn(v.z, v.w);
        uint2 u;
        u.x = *reinterpret_cast<unsigned*>(&h0);
        u.y = *reinterpret_cast<unsigned*>(&h1);
        ((uint2*)dst)[i] = u;
    }
}
// y in [0,5): Wq,Wk,Wg,Wv,Wo -> contiguous slabs (Woh follows Wallh directly)
__global__ void f2h5_kernel(const float* __restrict__ s0, const float* __restrict__ s1,
                            const float* __restrict__ s2, const float* __restrict__ s3,
                            const float* __restrict__ s4,
                            __half* __restrict__ dst, int n4)
{
    const float* src = (blockIdx.y == 0) ? s0 : (blockIdx.y == 1) ? s1
                       : (blockIdx.y == 2) ? s2 : (blockIdx.y == 3) ? s3 : s4;
    __half* d = dst + (size_t)blockIdx.y * (size_t)n4 * 4;
    int i = blockIdx.x * blockDim.x + threadIdx.x;
    const int stride = gridDim.x * blockDim.x;
    for (; i < n4; i += stride) {
        float4 v = ((const float4*)src)[i];
        __half2 h0 = __floats2half2_rn(v.x, v.y);
        __half2 h1 = __floats2half2_rn(v.z, v.w);
        uint2 u;
        u.x = *reinterpret_cast<unsigned*>(&h0);
        u.y = *reinterpret_cast<unsigned*>(&h1);
        ((uint2*)d)[i] = u;
    }
}

// ---------------- fp16 NT GEMM: 128x128 tile, warp 64x32 --------------------
// 3-stage cp.async pipeline with BK=64 stages (pitch 72 halves = 144B rows,
// conflict-free for ldmatrix: 144 mod 128 = 16 spreads 8 rows across distinct
// bank groups). One __syncthreads per 64-K iteration; 2 CTAs/SM.
#define KP 40                       // pitch for serial/inter (BK=32 kernels)
#define KP64 72                     // pitch for BK=64 GEMM stages
#define G64_STAGE (128 * KP64)      // halves per matrix per stage
#define G64_DSMEM (6 * G64_STAGE * 2)  // 3 stages x (A+B) = 110592 B

struct EpiPlain {
    const float* bias; float* C; int N; int act;
    __device__ __forceinline__ void store(int row, int col, float c0, float c1) const {
        c0 += __ldg(&bias[col]); c1 += __ldg(&bias[col + 1]);
        if (act) { c0 = 1.f / (1.f + expf(-c0)); c1 = 1.f / (1.f + expf(-c1)); }
        *(float2*)(C + (size_t)row * N + col) = make_float2(c0, c1);
    }
};
// routed epilogue: col>>10 selects one of 4 outputs (k,g get sigmoid)
struct EpiRoute {
    const float* b0; const float* b1; const float* b2; const float* b3;
    float* d0; float* d1; float* d2; float* d3;
    __device__ __forceinline__ void store(int row, int col, float c0, float c1) const {
        const int sel = col >> 10;
        const int lc = col & 1023;
        const float* bias = (sel == 0) ? b0 : (sel == 1) ? b1 : (sel == 2) ? b2 : b3;
        float* C = (sel == 0) ? d0 : (sel == 1) ? d1 : (sel == 2) ? d2 : d3;
        c0 += __ldg(&bias[lc]); c1 += __ldg(&bias[lc + 1]);
        if (sel == 1 || sel == 2) {
            c0 = 1.f / (1.f + expf(-c0)); c1 = 1.f / (1.f + expf(-c1));
        }
        *(float2*)(C + (size_t)row * 1024 + lc) = make_float2(c0, c1);
    }
};

template <class Epi>
__device__ __forceinline__ void gemm_body(
    const __half* __restrict__ A, const __half* __restrict__ B,
    int Kd, int bm, int bn, const Epi& epi)
{
    extern __shared__ __half gsm[];
    // stage s: As at gsm + s*G64_STAGE, Bs at gsm + (3+s)*G64_STAGE
    const int tid = threadIdx.x;
    const int lane = tid & 31;
    const int wid = tid >> 5;
    const int warpM = wid >> 2;
    const int warpN = wid & 3;

    float acc[4][4][4];
#pragma unroll
    for (int a = 0; a < 4; a++)
#pragma unroll
        for (int b = 0; b < 4; b++)
#pragma unroll
            for (int c = 0; c < 4; c++) acc[a][b][c] = 0.f;

    const int iters = Kd / 64;

    // stage loader: 128 rows x 64 halves per matrix; 4x16B chunks per thread each
#define LOAD_TILE64(stg, k0)                                                   \
    {                                                                          \
        __half* Asb = gsm + (stg) * G64_STAGE;                                 \
        __half* Bsb = gsm + (3 + (stg)) * G64_STAGE;                           \
        _Pragma("unroll")                                                      \
        for (int p = 0; p < 4; p++) {                                          \
            const int c = tid + p * 256;                                       \
            const int row = c >> 3;                                            \
            const int col = (c & 7) * 8;                                       \
            cp_async16(&Asb[row * KP64 + col],                                 \
                       A + (size_t)(bm + row) * Kd + (k0) + col);              \
            cp_async16(&Bsb[row * KP64 + col],                                 \
                       B + (size_t)(bn + row) * Kd + (k0) + col);              \
        }                                                                      \
    }

    LOAD_TILE64(0, 0);  CP_COMMIT();
    LOAD_TILE64(1, 64); CP_COMMIT();

    for (int it = 0; it < iters; ++it) {
        if (it + 1 < iters) { CP_WAIT(1); } else { CP_WAIT(0); }
        __syncthreads();   // tile it visible; prev iteration's readers done

        if (it + 2 < iters) {
            LOAD_TILE64((it + 2) % 3, (it + 2) * 64);
            CP_COMMIT();
        }

        const __half* Ab = gsm + (it % 3) * G64_STAGE;
        const __half* Bb = gsm + (3 + (it % 3)) * G64_STAGE;
#pragma unroll
        for (int ks = 0; ks < 4; ks++) {
            const int k0 = ks * 16;
            uint32_t afr[4][4];
            uint32_t bfr[4][2];
#pragma unroll
            for (int fm = 0; fm < 4; fm++) {
                const __half* p = &Ab[(warpM * 64 + fm * 16 + (lane & 7) +
                                       ((lane >> 3) & 1) * 8) * KP64 +
                                      k0 + (lane >> 4) * 8];
                ldm_x4(afr[fm], p);
            }
#pragma unroll
            for (int fp = 0; fp < 2; fp++) {
                uint32_t r[4];
                const __half* p = &Bb[(warpN * 32 + fp * 16 + (lane & 7) +
                                       (lane >> 4) * 8) * KP64 +
                                      k0 + ((lane >> 3) & 1) * 8];
                ldm_x4(r, p);
                bfr[2 * fp][0] = r[0];     bfr[2 * fp][1] = r[1];
                bfr[2 * fp + 1][0] = r[2]; bfr[2 * fp + 1][1] = r[3];
            }
#pragma unroll
            for (int fm = 0; fm < 4; fm++)
#pragma unroll
                for (int fn = 0; fn < 4; fn++)
                    mma16816(acc[fm][fn], afr[fm], bfr[fn]);
        }
    }
#undef LOAD_TILE64

#pragma unroll
    for (int fm = 0; fm < 4; fm++)
#pragma unroll
        for (int fn = 0; fn < 4; fn++)
#pragma unroll
            for (int h = 0; h < 2; h++) {
                const int row = bm + warpM * 64 + fm * 16 + (lane >> 2) + h * 8;
                const int col = bn + warpN * 32 + fn * 8 + (lane & 3) * 2;
                epi.store(row, col, acc[fm][fn][2 * h], acc[fm][fn][2 * h + 1]);
            }
}

__global__ void __launch_bounds__(256, 2) gemm_h_nt(
    const __half* __restrict__ A, const __half* __restrict__ B,
    const float* __restrict__ bias, float* __restrict__ C,
    int M, int N, int Kd, int act)
{
    EpiPlain epi{bias, C, N, act};
    gemm_body(A, B, Kd, blockIdx.y * 128, blockIdx.x * 128, epi);
}

// merged 4-projection GEMM: B = stacked [Wq;Wk;Wg;Wv] (4096 x 2048), routed epi
__global__ void __launch_bounds__(256, 2) gemm_h_nt_proj(
    const __half* __restrict__ A, const __half* __restrict__ Wall,
    const float* bq, const float* bk, const float* bg, const float* bv,
    float* qb, float* kb, float* gb, float* vb)
{
    EpiRoute epi{bq, bk, bg, bv, qb, kb, gb, vb};
    gemm_body(A, Wall, H_DIM, blockIdx.y * 128, blockIdx.x * 128, epi);
}

// ---------------- prep: per-chunk cumulative gates ----------------
__global__ void __launch_bounds__(256) prep_kernel(
    const float* __restrict__ q, const float* __restrict__ kk,
    const float* __restrict__ g, const float* __restrict__ vv,
    float* __restrict__ qa, __half* __restrict__ qah,
    float* __restrict__ kia, float* __restrict__ a15,
    __half* __restrict__ khT, __half* __restrict__ vT)
{
    const int cid = blockIdx.x;
    const int kc = threadIdx.x * 4;
    const size_t t0 = (size_t)cid * CHUNK;
    float4 A = make_float4(1.f, 1.f, 1.f, 1.f);
#pragma unroll 4
    for (int u = 0; u < CHUNK; u++) {
        const size_t off = (t0 + u) * K_DIM + kc;
        float4 gv = *(const float4*)(g + off);
        A.x *= gv.x; A.y *= gv.y; A.z *= gv.z; A.w *= gv.w;
        float4 qv = *(const float4*)(q + off);
        float4 qa4 = make_float4(qv.x * A.x, qv.y * A.y, qv.z * A.z, qv.w * A.w);
        *(float4*)(qa + off) = qa4;
        __half2 h0 = __floats2half2_rn(qa4.x, qa4.y);
        __half2 h1 = __floats2half2_rn(qa4.z, qa4.w);
        uint2 uu; uu.x = *(unsigned*)&h0; uu.y = *(unsigned*)&h1;
        *(uint2*)(qah + off) = uu;
        float4 kv = *(const float4*)(kk + off);
        float4 ki = make_float4(__fdiv_rn(kv.x, A.x), __fdiv_rn(kv.y, A.y),
                                __fdiv_rn(kv.z, A.z), __fdiv_rn(kv.w, A.w));
        *(float4*)(kia + off) = ki;
    }
    *(float4*)(a15 + (size_t)cid * K_DIM + kc) = A;

    {
        uint32_t buf[4][16];
        float prev[4];
#pragma unroll
        for (int u = 0; u < CHUNK; u++) {
            const size_t off = (t0 + u) * K_DIM + kc;
            float4 ki = *(const float4*)(kia + off);
            float cur[4] = {ki.x * A.x, ki.y * A.y, ki.z * A.z, ki.w * A.w};
            if (u & 1) {
#pragma unroll
                for (int j = 0; j < 4; j++) {
                    __half2 h = __floats2half2_rn(prev[j], cur[j]);
                    buf[j][u >> 1] = *(unsigned*)&h;
                }
            } else {
#pragma unroll
                for (int j = 0; j < 4; j++) prev[j] = cur[j];
            }
        }
#pragma unroll
        for (int j = 0; j < 4; j++) {
            __half* dst = khT + ((size_t)cid * K_DIM + kc + j) * CHUNK;
#pragma unroll
            for (int c = 0; c < 4; c++)
                *(uint4*)(dst + c * 8) = *(uint4*)&buf[j][c * 4];
        }
    }
    {
        uint32_t buf[4][16];
        float prev[4];
#pragma unroll
        for (int u = 0; u < CHUNK; u++) {
            float4 v4 = *(const float4*)(vv + (t0 + u) * V_DIM + kc);
            float cur[4] = {v4.x, v4.y, v4.z, v4.w};
            if (u & 1) {
#pragma unroll
                for (int j = 0; j < 4; j++) {
                    __half2 h = __floats2half2_rn(prev[j], cur[j]);
                    buf[j][u >> 1] = *(unsigned*)&h;
                }
            } else {
#pragma unroll
                for (int j = 0; j < 4; j++) prev[j] = cur[j];
            }
        }
#pragma unroll
        for (int j = 0; j < 4; j++) {
            __half* dst = vT + ((size_t)cid * V_DIM + kc + j) * CHUNK;
#pragma unroll
            for (int c = 0; c < 4; c++)
                *(uint4*)(dst + c * 8) = *(uint4*)&buf[j][c * 4];
        }
    }
}

// ---------------- intra-chunk: P = QA @ KIA^T (masked), out = P @ V ----------
#define TS 128
__global__ void __launch_bounds__(256) intra_kernel(
    const float* __restrict__ qa, const float* __restrict__ kia,
    const float* __restrict__ vv, float* __restrict__ opre)
{
    __shared__ float qs[CHUNK][TS + 4];
    __shared__ float ks_[CHUNK][TS + 4];
    __shared__ float Ps[CHUNK][CHUNK + 1];
    const int tid = threadIdx.x;
    const int cid = blockIdx.x;
    const size_t t0 = (size_t)cid * CHUNK;

    for (int i = tid; i < CHUNK * (CHUNK + 1); i += 256)
        ((float*)Ps)[i] = 0.f;

    const int u0 = ((tid >> 2) & 3) * 8;
    const int s0 = (tid & 3) * 8;
    const int ksl = tid >> 4;
    float acc[8][8];
#pragma unroll
    for (int i = 0; i < 8; i++)
#pragma unroll
        for (int j = 0; j < 8; j++) acc[i][j] = 0.f;

    for (int kt = 0; kt < K_DIM; kt += TS) {
        __syncthreads();
#pragma unroll
        for (int p = 0; p < 4; p++) {
            int idx = tid + p * 256;
            int rr = idx >> 5;
            int cc = (idx & 31) * 4;
            *(float4*)&qs[rr][cc]  = *(const float4*)(qa  + (t0 + rr) * K_DIM + kt + cc);
            *(float4*)&ks_[rr][cc] = *(const float4*)(kia + (t0 + rr) * K_DIM + kt + cc);
        }
        __syncthreads();
        const int kb = ksl * 8;
#pragma unroll
        for (int km = 0; km < 8; km++) {
            const int kx = kb + km;
            float qv[8], kv[8];
#pragma unroll
            for (int i = 0; i < 8; i++) qv[i] = qs[u0 + i][kx];
#pragma unroll
            for (int j = 0; j < 8; j++) kv[j] = ks_[s0 + j][kx];
#pragma unroll
            for (int i = 0; i < 8; i++)
#pragma unroll
                for (int j = 0; j < 8; j++)
                    acc[i][j] = fmaf(qv[i], kv[j], acc[i][j]);
        }
    }
    __syncthreads();
#pragma unroll
    for (int i = 0; i < 8; i++)
#pragma unroll
        for (int j = 0; j < 8; j++)
            atomicAdd(&Ps[u0 + i][s0 + j], acc[i][j]);
    __syncthreads();

    const int vc = tid * 4;
#pragma unroll
    for (int pass = 0; pass < 4; pass++) {
        float o[8][4];
#pragma unroll
        for (int i = 0; i < 8; i++) { o[i][0] = o[i][1] = o[i][2] = o[i][3] = 0.f; }
        for (int s = 0; s < CHUNK; s++) {
            float4 v4 = *(const float4*)(vv + (t0 + s) * V_DIM + vc);
#pragma unroll
            for (int i = 0; i < 8; i++) {
                const int u = pass * 8 + i;
                float p = (s <= u) ? Ps[u][s] : 0.f;
                o[i][0] = fmaf(p, v4.x, o[i][0]);
                o[i][1] = fmaf(p, v4.y, o[i][1]);
                o[i][2] = fmaf(p, v4.z, o[i][2]);
                o[i][3] = fmaf(p, v4.w, o[i][3]);
            }
        }
#pragma unroll
        for (int i = 0; i < 8; i++) {
            const int u = pass * 8 + i;
            *(float4*)(opre + (t0 + u) * V_DIM + vc) =
                make_float4(o[i][0], o[i][1], o[i][2], o[i][3]);
        }
    }
}

// ---------------- serial v4: double-buffered tensor-core state updates ------
#define SER_DSMEM 54016
__global__ void __launch_bounds__(256, 2) serial_kernel4(
    const __half* __restrict__ khT, const __half* __restrict__ vT,
    const float* __restrict__ a15, __half* __restrict__ snap,
    float* __restrict__ state_out)
{
    extern __shared__ char dyn[];
    __half* khsA[2] = {(__half*)(dyn),         (__half*)(dyn + 20480)};
    __half* vsA[2]  = {(__half*)(dyn + 40960), (__half*)(dyn + 42240)};
    float*  a15A[2] = {(float*)(dyn + 43520),  (float*)(dyn + 44544)};
    __half* snapS   = (__half*)(dyn + 45568);

    const int tid = threadIdx.x;
    const int lane = tid & 31;
    const int wid = tid >> 5;
    const int kg = blockIdx.x & 3;
    const int vsb = blockIdx.x >> 2;
    const int kbaseCTA = kg * 256;
    const int vbase = vsb * 16;

#define SER_PREF(c, b)                                                         \
    {                                                                          \
        const __half* kSrc = khT + ((size_t)(c) * K_DIM + kbaseCTA) * CHUNK;   \
        _Pragma("unroll")                                                      \
        for (int p = 0; p < 4; p++) {                                          \
            const int idx = tid + p * 256;                                     \
            const int row = idx >> 2;                                          \
            const int cc = (idx & 3) * 8;                                      \
            cp_async16(&khsA[b][row * KP + cc], kSrc + row * CHUNK + cc);      \
        }                                                                      \
        if (tid < 64) {                                                        \
            const int row = tid >> 2;                                          \
            const int cc = (tid & 3) * 8;                                      \
            cp_async16(&vsA[b][row * KP + cc],                                 \
                       vT + ((size_t)(c) * V_DIM + vbase + row) * CHUNK + cc); \
        } else if (tid < 128) {                                                \
            const int j = tid - 64;                                            \
            cp_async16_g(&a15A[b][j * 4],                                      \
                         a15 + (size_t)(c) * K_DIM + kbaseCTA + j * 4);        \
        }                                                                      \
        CP_COMMIT();                                                           \
    }

    float acc[2][2][4];
#pragma unroll
    for (int mt = 0; mt < 2; mt++)
#pragma unroll
        for (int nt = 0; nt < 2; nt++)
#pragma unroll
            for (int c = 0; c < 4; c++) acc[mt][nt][c] = 0.f;

    SER_PREF(0, 0);

    for (int cid = 0; cid < NCHUNK; cid++) {
        const int buf = cid & 1;

#pragma unroll
        for (int mt = 0; mt < 2; mt++)
#pragma unroll
            for (int nt = 0; nt < 2; nt++)
#pragma unroll
                for (int h = 0; h < 2; h++) {
                    const int row = wid * 32 + mt * 16 + (lane >> 2) + h * 8;
                    const int col = nt * 8 + (lane & 3) * 2;
                    snapS[col * 264 + row]       = __float2half(acc[mt][nt][2 * h]);
                    snapS[(col + 1) * 264 + row] = __float2half(acc[mt][nt][2 * h + 1]);
                }
        __syncthreads();

        if (cid + 1 < NCHUNK) SER_PREF(cid + 1, buf ^ 1);

        for (int idx = tid; idx < 512; idx += 256) {
            const int vr = idx >> 5;
            const int kc16 = idx & 31;
            uint4 val = *(uint4*)&snapS[vr * 264 + kc16 * 8];
            *(uint4*)(snap + ((size_t)cid * V_DIM + vbase + vr) * K_DIM +
                      kbaseCTA + kc16 * 8) = val;
        }

        if (cid + 1 < NCHUNK) { CP_WAIT(1); } else { CP_WAIT(0); }
        __syncthreads();

#pragma unroll
        for (int mt = 0; mt < 2; mt++)
#pragma unroll
            for (int h = 0; h < 2; h++) {
                const float av = a15A[buf][wid * 32 + mt * 16 + (lane >> 2) + h * 8];
#pragma unroll
                for (int nt = 0; nt < 2; nt++) {
                    acc[mt][nt][2 * h]     *= av;
                    acc[mt][nt][2 * h + 1] *= av;
                }
            }

#pragma unroll
        for (int ks = 0; ks < 2; ks++) {
            const int k0 = ks * 16;
            uint32_t afr[2][4];
            uint32_t bfr[2][2];
#pragma unroll
            for (int mt = 0; mt < 2; mt++) {
                const __half* p = &khsA[buf][(wid * 32 + mt * 16 + (lane & 7) +
                                              ((lane >> 3) & 1) * 8) * KP +
                                             k0 + (lane >> 4) * 8];
                ldm_x4(afr[mt], p);
            }
            {
                uint32_t r[4];
                const __half* p = &vsA[buf][((lane & 7) + (lane >> 4) * 8) * KP +
                                            k0 + ((lane >> 3) & 1) * 8];
                ldm_x4(r, p);
                bfr[0][0] = r[0]; bfr[0][1] = r[1];
                bfr[1][0] = r[2]; bfr[1][1] = r[3];
            }
#pragma unroll
            for (int mt = 0; mt < 2; mt++)
#pragma unroll
                for (int nt = 0; nt < 2; nt++)
                    mma16816(acc[mt][nt], afr[mt], bfr[nt]);
        }
    }
#undef SER_PREF

#pragma unroll
    for (int mt = 0; mt < 2; mt++)
#pragma unroll
        for (int nt = 0; nt < 2; nt++)
#pragma unroll
            for (int h = 0; h < 2; h++) {
                const int row = kbaseCTA + wid * 32 + mt * 16 + (lane >> 2) + h * 8;
                const int col = vbase + nt * 8 + (lane & 3) * 2;
                *(float2*)(state_out + (size_t)row * V_DIM + col) =
                    make_float2(acc[mt][nt][2 * h], acc[mt][nt][2 * h + 1]);
            }
}

// ---------------- inter: opre += qa_chunk @ snapshot^T (mma.sync) -----------
__global__ void __launch_bounds__(256) inter_kernel(
    const __half* __restrict__ qah, const __half* __restrict__ snap,
    float* __restrict__ opre)
{
    __shared__ __half As[2][32 * KP];
    __shared__ __half Bs[2][128 * KP];
    const int tid = threadIdx.x;
    const int lane = tid & 31;
    const int wid = tid >> 5;
    const int warpM = wid >> 2;
    const int warpN = wid & 3;
    const int vt = blockIdx.x;
    const int cid = blockIdx.y + 1;

    const __half* A = qah + (size_t)cid * CHUNK * K_DIM;
    const __half* B = snap + ((size_t)cid * V_DIM + vt * 128) * K_DIM;

    float acc[4][4];
#pragma unroll
    for (int a = 0; a < 4; a++)
#pragma unroll
        for (int c = 0; c < 4; c++) acc[a][c] = 0.f;

#define LOAD_TILE_I(buf, k0)                                                   \
    {                                                                          \
        if (tid < 128) {                                                       \
            const int row = tid >> 2;                                          \
            const int col = (tid & 3) * 8;                                     \
            cp_async16(&As[buf][row * KP + col],                               \
                       A + (size_t)row * K_DIM + (k0) + col);                  \
        }                                                                      \
        _Pragma("unroll")                                                      \
        for (int p = 0; p < 2; p++) {                                          \
            const int c = tid + p * 256;                                       \
            const int row = c >> 2;                                            \
            const int col = (c & 3) * 8;                                       \
            cp_async16(&Bs[buf][row * KP + col],                               \
                       B + (size_t)row * K_DIM + (k0) + col);                  \
        }                                                                      \
    }

    LOAD_TILE_I(0, 0);
    CP_COMMIT();
    const int iters = K_DIM / 32;
    for (int it = 0; it < iters; ++it) {
        if (it + 1 < iters) {
            LOAD_TILE_I((it + 1) & 1, (it + 1) * 32);
            CP_COMMIT();
            CP_WAIT(1);
        } else {
            CP_WAIT(0);
        }
        __syncthreads();
        const __half* Ab = As[it & 1];
        const __half* Bb = Bs[it & 1];
#pragma unroll
        for (int ks = 0; ks < 2; ks++) {
            const int k0 = ks * 16;
            uint32_t afr[4];
            uint32_t bfr[4][2];
            {
                const __half* p = &Ab[(warpM * 16 + (lane & 7) +
                                       ((lane >> 3) & 1) * 8) * KP +
                                      k0 + (lane >> 4) * 8];
                ldm_x4(afr, p);
            }
#pragma unroll
            for (int fp = 0; fp < 2; fp++) {
                uint32_t r[4];
                const __half* p = &Bb[(warpN * 32 + fp * 16 + (lane & 7) +
                                       (lane >> 4) * 8) * KP +
                                      k0 + ((lane >> 3) & 1) * 8];
                ldm_x4(r, p);
                bfr[2 * fp][0] = r[0];     bfr[2 * fp][1] = r[1];
                bfr[2 * fp + 1][0] = r[2]; bfr[2 * fp + 1][1] = r[3];
            }
#pragma unroll
            for (int fn = 0; fn < 4; fn++) mma16816(acc[fn], afr, bfr[fn]);
        }
        __syncthreads();
    }
#undef LOAD_TILE_I

#pragma unroll
    for (int fn = 0; fn < 4; fn++)
#pragma unroll
        for (int h = 0; h < 2; h++) {
            const int row = cid * CHUNK + warpM * 16 + (lane >> 2) + h * 8;
            const int col = vt * 128 + warpN * 32 + fn * 8 + (lane & 3) * 2;
            float2 o = *(float2*)(opre + (size_t)row * V_DIM + col);
            o.x += acc[fn][2 * h];
            o.y += acc[fn][2 * h + 1];
            *(float2*)(opre + (size_t)row * V_DIM + col) = o;
        }
}

// ---------------------------------------------------------------------------
extern "C" void kernel_launch(void* const* d_in, const int* in_sizes, int n_in,
                              void* d_out, int out_size)
{
    const float* X  = (const float*)d_in[0];
    const float* Wq = (const float*)d_in[1];
    const float* bq = (const float*)d_in[2];
    const float* Wk = (const float*)d_in[3];
    const float* bk = (const float*)d_in[4];
    const float* Wv = (const float*)d_in[5];
    const float* bv = (const float*)d_in[6];
    const float* Wg = (const float*)d_in[7];
    const float* bg = (const float*)d_in[8];
    const float* Wo = (const float*)d_in[9];
    const float* bo = (const float*)d_in[10];
    float* out = (float*)d_out;

    float* scratch = 0;
    cudaGetSymbolAddress((void**)&scratch, g_scratch);
    float* qb    = scratch;
    float* kb    = qb   + (size_t)T_DIM * K_DIM;
    float* gb    = kb   + (size_t)T_DIM * K_DIM;
    float* vb    = gb   + (size_t)T_DIM * K_DIM;
    float* qa    = vb   + (size_t)T_DIM * V_DIM;
    float* kia   = qa   + (size_t)T_DIM * K_DIM;
    float* opre  = kia  + (size_t)T_DIM * K_DIM;
    float* a15   = opre + (size_t)T_DIM * V_DIM;
    float* sdump = a15  + (size_t)NCHUNK * K_DIM;

    __half* hscr = 0;
    cudaGetSymbolAddress((void**)&hscr, g_scratch_h);
    __half* Xh    = hscr;
    __half* Wallh = Xh    + (size_t)T_DIM * H_DIM;
    __half* Woh   = Wallh + (size_t)4 * K_DIM * H_DIM;
    __half* opreh = Woh   + (size_t)O_DIM * V_DIM;
    __half* qah   = opreh + (size_t)T_DIM * V_DIM;
    __half* khT   = qah   + (size_t)T_DIM * K_DIM;
    __half* vT    = khT   + (size_t)T_DIM * K_DIM;
    __half* snap  = vT    + (size_t)T_DIM * K_DIM;

    const size_t out_main = (size_t)T_DIM * O_DIM;
    const size_t out_full = out_main + (size_t)K_DIM * V_DIM;
    float* state_out = ((size_t)out_size >= out_full) ? (out + out_main) : sdump;

    // opt-in dynamic smem (host API only; idempotent)
    cudaFuncSetAttribute(gemm_h_nt, cudaFuncAttributeMaxDynamicSharedMemorySize, G64_DSMEM);
    cudaFuncSetAttribute(gemm_h_nt_proj, cudaFuncAttributeMaxDynamicSharedMemorySize, G64_DSMEM);
    cudaFuncSetAttribute(serial_kernel4, cudaFuncAttributeMaxDynamicSharedMemorySize,
                         SER_DSMEM);

    dim3 blk(256);

    f2h_kernel<<<2048, 256>>>(X, Xh, (int)((size_t)T_DIM * H_DIM / 4));
    // 5 weight slabs (Wq,Wk,Wg,Wv,Wo) are contiguous in g_scratch_h and all
    // K_DIM*H_DIM elements (Wo = O*V = same count) -> one batched convert
    f2h5_kernel<<<dim3(512, 5), 256>>>(Wq, Wk, Wg, Wv, Wo, Wallh,
                                       (int)((size_t)K_DIM * H_DIM / 4));

    // merged projection GEMM: 3-stage BK=64 pipeline, one barrier per 64-K
    gemm_h_nt_proj<<<dim3(4 * K_DIM / 128, T_DIM / 128), blk, G64_DSMEM>>>(
        Xh, Wallh, bq, bk, bg, bv, qb, kb, gb, vb);

    // chunked gated-linear-attention pipeline
    prep_kernel<<<NCHUNK, blk>>>(qb, kb, gb, vb, qa, qah, kia, a15, khT, vT);
    intra_kernel<<<NCHUNK, blk>>>(qa, kia, vb, opre);
    serial_kernel4<<<256, blk, SER_DSMEM>>>(khT, vT, a15, snap, state_out);
    inter_kernel<<<dim3(8, NCHUNK - 1), blk>>>(qah, snap, opre);

    // opre -> fp16, output projection
    f2h_kernel<<<1024, 256>>>(opre, opreh, (int)((size_t)T_DIM * V_DIM / 4));
    gemm_h_nt<<<dim3(O_DIM / 128, T_DIM / 128), blk, G64_DSMEM>>>(opreh, Woh, bo, out,
                                                                  T_DIM, O_DIM, V_DIM, 0);
}